// round 2
// baseline (speedup 1.0000x reference)
#include <cuda_runtime.h>

#define PI_F 3.14159265358979f

// ---------------- device-global scratch (allocation-free) ----------------
__device__ float  d_style_ang[48];     // [b][i] = pi*tanh(style proj)
__device__ float  d_alpha0[6];         // layer-0 RY angle
__device__ float  d_cb0[6], d_sb0[6];  // cos/sin(beta0/2)
__device__ float2 d_g1[6][4];          // layer-1 combined RZ*RY 2x2 gates
__device__ float2 d_g2[6][4];          // measurement U3 2x2 gates
__device__ float  d_Wqs[64 * 64];      // Wq[s][c] = sum_i out_w[c,i]*sign_i(s)
__device__ float  d_phi[32768 * 6];    // per-pixel per-wire encoding angle

// ---------------- packed f32x2 helpers ----------------
__device__ __forceinline__ unsigned long long pk2(float lo, float hi) {
    unsigned long long r;
    asm("mov.b64 %0, {%1, %2};" : "=l"(r) : "f"(lo), "f"(hi));
    return r;
}
__device__ __forceinline__ void upk2(float& lo, float& hi, unsigned long long v) {
    asm("mov.b64 {%0, %1}, %2;" : "=f"(lo), "=f"(hi) : "l"(v));
}
__device__ __forceinline__ void fma2(unsigned long long& d, unsigned long long a,
                                     unsigned long long b) {
    // d = a * b + d  (per-half fp32)
    asm("fma.rn.f32x2 %0, %1, %2, %0;" : "+l"(d) : "l"(a), "l"(b));
}

// ---------------- setup ----------------
__global__ void k_setup(const float* __restrict__ style,
                        const float* __restrict__ sw, const float* __restrict__ sb,
                        const float* __restrict__ qcnn, const float* __restrict__ meas,
                        const float* __restrict__ ow) {
    int tid = threadIdx.x;
    int warp = tid >> 5, lane = tid & 31;
    const unsigned F = 0xffffffffu;
    // 48 style dot products, warp each
    for (int task = warp; task < 48; task += 8) {
        int bi = task / 6, i = task - bi * 6;
        const float4 a = reinterpret_cast<const float4*>(style + bi * 128)[lane];
        const float4 w = reinterpret_cast<const float4*>(sw + i * 128)[lane];
        float acc = a.x * w.x + a.y * w.y + a.z * w.z + a.w * w.w;
#pragma unroll
        for (int o = 16; o; o >>= 1) acc += __shfl_xor_sync(F, acc, o);
        if (lane == 0) d_style_ang[task] = PI_F * tanhf(acc + sb[i]);
    }
    if (tid < 6) {
        int i = tid;
        float a0 = qcnn[(i * 2 + 0) * 3];
        float b0 = qcnn[(i * 2 + 1) * 3];
        d_alpha0[i] = a0;
        d_cb0[i] = cosf(0.5f * b0);
        d_sb0[i] = sinf(0.5f * b0);
        float a1 = qcnn[((6 + i) * 2 + 0) * 3];
        float b1 = qcnn[((6 + i) * 2 + 1) * 3];
        float ca = cosf(0.5f * a1), sa = sinf(0.5f * a1);
        float cb = cosf(0.5f * b1), sbv = sinf(0.5f * b1);
        d_g1[i][0] = make_float2(cb * ca, -sbv * ca);
        d_g1[i][1] = make_float2(-cb * sa, sbv * sa);
        d_g1[i][2] = make_float2(cb * sa, sbv * sa);
        d_g1[i][3] = make_float2(cb * ca, sbv * ca);
        float th = meas[i * 3 + 0], phv = meas[i * 3 + 1], la = meas[i * 3 + 2];
        float ct = cosf(0.5f * th), st = sinf(0.5f * th);
        d_g2[i][0] = make_float2(ct, 0.f);
        d_g2[i][1] = make_float2(-cosf(la) * st, -sinf(la) * st);
        d_g2[i][2] = make_float2(cosf(phv) * st, sinf(phv) * st);
        d_g2[i][3] = make_float2(cosf(phv + la) * ct, sinf(phv + la) * ct);
    }
    for (int idx = tid; idx < 4096; idx += blockDim.x) {
        int s = idx >> 6, c = idx & 63;
        float acc = 0.f;
#pragma unroll
        for (int i = 0; i < 6; i++)
            acc += ow[c * 6 + i] * (((s >> (5 - i)) & 1) ? -1.f : 1.f);
        d_Wqs[idx] = acc;  // [s][c]
    }
}

// ---------------- fused conv (res 64ch + data 6ch), FFMA2 packed ----------------
// grid 128 blocks; block 512 thr; tile = 8h x 32w, 64 co.
// thread: pw = tid&31 (w), cg = (tid>>5)&7 (co group of 8, packed as 4 f32x2 pairs),
// phb = (tid>>8)*4 (row half: rows phb..phb+3).
__global__ __launch_bounds__(512) void k_conv(
    const float* __restrict__ x, const float* __restrict__ wr,
    const float* __restrict__ rb, const float* __restrict__ wd,
    const float* __restrict__ db, float* __restrict__ out) {
    __shared__ float xs[8][10][34];
    __shared__ float ws[72][66];   // 66: keeps float2 pairs 8B-aligned
    __shared__ float wds[72][8];
    int blk = blockIdx.x;
    int b = blk >> 4;
    int ti = blk & 15;
    int h0 = (ti >> 1) << 3;
    int w0 = (ti & 1) << 5;
    int tid = threadIdx.x;
    int pw = tid & 31;
    int cg = (tid >> 5) & 7;
    int phb = (tid >> 8) << 2;

    unsigned long long acc2[4][4];   // [ph][co-pair]; co = cg*8 + 2j (+1)
#pragma unroll
    for (int a = 0; a < 4; a++)
#pragma unroll
        for (int j = 0; j < 4; j++) acc2[a][j] = 0ULL;
    float accd[4] = {0.f, 0.f, 0.f, 0.f};

    const float* xb = x + b * 262144;

    for (int chunk = 0; chunk < 8; chunk++) {
        int ci0 = chunk << 3;
        __syncthreads();
        for (int i = tid; i < 2720; i += 512) {
            int ci = i / 340; int rem = i - ci * 340;
            int r = rem / 34; int cpos = rem - r * 34;
            int gh = h0 - 1 + r, gw = w0 - 1 + cpos;
            float v = 0.f;
            if ((unsigned)gh < 64u && (unsigned)gw < 64u)
                v = xb[((ci0 + ci) << 12) + (gh << 6) + gw];
            xs[ci][r][cpos] = v;
        }
        for (int i = tid; i < 4608; i += 512) {
            int c = i / 72, k = i - c * 72;
            ws[k][c] = wr[c * 576 + ci0 * 9 + k];
        }
        for (int i = tid; i < 432; i += 512) {
            int c = i / 72, k = i - c * 72;
            wds[k][c] = wd[c * 576 + ci0 * 9 + k];
        }
        __syncthreads();

        for (int cil = 0; cil < 8; cil++) {
#pragma unroll
            for (int kh = 0; kh < 3; kh++) {
#pragma unroll
                for (int kw = 0; kw < 3; kw++) {
                    int k = cil * 9 + kh * 3 + kw;
                    float xr[4];
                    unsigned long long xx[4];
#pragma unroll
                    for (int ph = 0; ph < 4; ph++) {
                        xr[ph] = xs[cil][kh + phb + ph][kw + pw];
                        xx[ph] = pk2(xr[ph], xr[ph]);
                    }
                    unsigned long long w2[4];
#pragma unroll
                    for (int j = 0; j < 4; j++)
                        w2[j] = *reinterpret_cast<const unsigned long long*>(
                            &ws[k][(cg << 3) + (j << 1)]);
#pragma unroll
                    for (int ph = 0; ph < 4; ph++)
#pragma unroll
                        for (int j = 0; j < 4; j++)
                            fma2(acc2[ph][j], w2[j], xx[ph]);
                    if (cg < 6) {
                        float wdv = wds[k][cg];
#pragma unroll
                        for (int ph = 0; ph < 4; ph++)
                            accd[ph] = fmaf(xr[ph], wdv, accd[ph]);
                    }
                }
            }
        }
    }

    // epilogue: residual conv + bias
#pragma unroll
    for (int j = 0; j < 4; j++) {
        int co = (cg << 3) + (j << 1);
        float b0v = rb[co], b1v = rb[co + 1];
#pragma unroll
        for (int ph = 0; ph < 4; ph++) {
            float lo, hi;
            upk2(lo, hi, acc2[ph][j]);
            int row = ((b * 64 + co) << 12) + ((h0 + phb + ph) << 6) + w0 + pw;
            out[row] = lo + b0v;
            out[row + 4096] = hi + b1v;
        }
    }
    // data channel -> encoding angle phi
    if (cg < 6) {
        float sa_ = d_style_ang[b * 6 + cg] + d_alpha0[cg];
        float bias = db[cg];
#pragma unroll
        for (int ph = 0; ph < 4; ph++) {
            int p = (b << 12) + ((h0 + phb + ph) << 6) + w0 + pw;
            d_phi[p * 6 + cg] = PI_F * tanhf(accd[ph] + bias) + sa_;
        }
    }
}

// ---------------- quantum sim: warp per pixel, 2 amps per lane ----------------
// state s (6 bits): wire i <-> bit (5-i). slot0: s=lane, slot1: s=lane+32.
__device__ __forceinline__ void gate_b5(const float2* __restrict__ G,
                                        float& a0r, float& a0i, float& a1r, float& a1i) {
    float2 g00 = G[0], g01 = G[1], g10 = G[2], g11 = G[3];
    float n0r = g00.x * a0r - g00.y * a0i + g01.x * a1r - g01.y * a1i;
    float n0i = g00.x * a0i + g00.y * a0r + g01.x * a1i + g01.y * a1r;
    float n1r = g10.x * a0r - g10.y * a0i + g11.x * a1r - g11.y * a1i;
    float n1i = g10.x * a0i + g10.y * a0r + g11.x * a1i + g11.y * a1r;
    a0r = n0r; a0i = n0i; a1r = n1r; a1i = n1i;
}

__device__ __forceinline__ void gate_lo(int bbit, int lane, const float2* __restrict__ G,
                                        float& a0r, float& a0i, float& a1r, float& a1i) {
    const unsigned F = 0xffffffffu;
    float2 g00 = G[0], g01 = G[1], g10 = G[2], g11 = G[3];
    int m = 1 << bbit;
    float p0r = __shfl_xor_sync(F, a0r, m);
    float p0i = __shfl_xor_sync(F, a0i, m);
    float p1r = __shfl_xor_sync(F, a1r, m);
    float p1i = __shfl_xor_sync(F, a1i, m);
    bool hi = (lane >> bbit) & 1;
    float Ar = hi ? g11.x : g00.x, Ai = hi ? g11.y : g00.y;
    float Pr = hi ? g10.x : g01.x, Pi = hi ? g10.y : g01.y;
    float n0r = Ar * a0r - Ai * a0i + Pr * p0r - Pi * p0i;
    float n0i = Ar * a0i + Ai * a0r + Pr * p0i + Pi * p0r;
    float n1r = Ar * a1r - Ai * a1i + Pr * p1r - Pi * p1i;
    float n1i = Ar * a1i + Ai * a1r + Pr * p1i + Pi * p1r;
    a0r = n0r; a0i = n0i; a1r = n1r; a1i = n1i;
}

// composed CNOT-ring permutation source index (GF(2)-linear).
// Ring = T1..T6 with Ti: psi'[s]=psi[Gi(s)]; Q = G1∘G2∘...∘G6.
__device__ __forceinline__ int ring_src(int s) {
    int b5 = (s >> 5) & 1, b4 = (s >> 4) & 1, b3 = (s >> 3) & 1;
    int b2 = (s >> 2) & 1, b1 = (s >> 1) & 1, b0 = s & 1;
    b5 ^= b0;   // G6
    b0 ^= b1;   // G5
    b1 ^= b2;   // G4
    b2 ^= b3;   // G3
    b3 ^= b4;   // G2
    b4 ^= b5;   // G1 (uses updated b5)
    return (b5 << 5) | (b4 << 4) | (b3 << 3) | (b2 << 2) | (b1 << 1) | b0;
}

__device__ __forceinline__ void ring2(int q0l, int q0h, int q1l, int q1h,
                                      float& a0r, float& a0i, float& a1r, float& a1i) {
    const unsigned F = 0xffffffffu;
    float x0r = __shfl_sync(F, a0r, q0l);
    float y0r = __shfl_sync(F, a1r, q0l);
    float x0i = __shfl_sync(F, a0i, q0l);
    float y0i = __shfl_sync(F, a1i, q0l);
    float x1r = __shfl_sync(F, a0r, q1l);
    float y1r = __shfl_sync(F, a1r, q1l);
    float x1i = __shfl_sync(F, a0i, q1l);
    float y1i = __shfl_sync(F, a1i, q1l);
    a0r = q0h ? y0r : x0r; a0i = q0h ? y0i : x0i;
    a1r = q1h ? y1r : x1r; a1i = q1h ? y1i : x1i;
}

// grid 512 blocks; block 256 (8 warps); block = 64 consecutive pixels, 8 per warp.
__global__ __launch_bounds__(256) void k_quant(const float* __restrict__ ob,
                                               float* __restrict__ out) {
    __shared__ float wq[64][64];   // [s][c]
    __shared__ float shp[8][64];
    __shared__ float sho[64][65];  // [c][px]
    const unsigned F = 0xffffffffu;
    int tid = threadIdx.x;
    for (int i = tid; i < 4096; i += 256) wq[i >> 6][i & 63] = d_Wqs[i];

    int warp = tid >> 5, lane = tid & 31;
    int q0 = ring_src(lane), q1 = ring_src(lane + 32);
    int q0l = q0 & 31, q0h = q0 >> 5;
    int q1l = q1 & 31, q1h = q1 >> 5;
    float ob0 = ob[lane], ob1 = ob[lane + 32];
    int pbase = blockIdx.x << 6;
    __syncthreads();

    for (int it = 0; it < 8; it++) {
        int p = pbase + (it << 3) + warp;
        float myphi = 0.f;
        if (lane < 6) myphi = d_phi[p * 6 + lane];

        float u0r[6], u0i[6], u1r[6], u1i[6];
#pragma unroll
        for (int i = 0; i < 6; i++) {
            float ph = __shfl_sync(F, myphi, i);
            float sv, cv;
            __sincosf(0.5f * ph, &sv, &cv);
            float cb = d_cb0[i], sb = d_sb0[i];
            u0r[i] = cv * cb; u0i[i] = -cv * sb;
            u1r[i] = sv * cb; u1i[i] = sv * sb;
        }
        float a0r = 1.f, a0i = 0.f, a1r, a1i;
#pragma unroll
        for (int i = 0; i < 6; i++) {
            int bit = (lane >> (5 - i)) & 1;
            float ur = bit ? u1r[i] : u0r[i];
            float ui = bit ? u1i[i] : u0i[i];
            float nr = a0r * ur - a0i * ui;
            float ni = a0r * ui + a0i * ur;
            a0r = nr; a0i = ni;
        }
        a1r = u1r[0]; a1i = u1i[0];
#pragma unroll
        for (int i = 1; i < 6; i++) {
            int bit = (lane >> (5 - i)) & 1;
            float ur = bit ? u1r[i] : u0r[i];
            float ui = bit ? u1i[i] : u0i[i];
            float nr = a1r * ur - a1i * ui;
            float ni = a1r * ui + a1i * ur;
            a1r = nr; a1i = ni;
        }

        ring2(q0l, q0h, q1l, q1h, a0r, a0i, a1r, a1i);
#pragma unroll
        for (int i = 0; i < 6; i++) {
            if (i == 0) gate_b5(d_g1[0], a0r, a0i, a1r, a1i);
            else        gate_lo(5 - i, lane, d_g1[i], a0r, a0i, a1r, a1i);
        }
        ring2(q0l, q0h, q1l, q1h, a0r, a0i, a1r, a1i);
#pragma unroll
        for (int i = 0; i < 6; i++) {
            if (i == 0) gate_b5(d_g2[0], a0r, a0i, a1r, a1i);
            else        gate_lo(5 - i, lane, d_g2[i], a0r, a0i, a1r, a1i);
        }

        shp[warp][lane] = a0r * a0r + a0i * a0i;
        shp[warp][lane + 32] = a1r * a1r + a1i * a1i;
        __syncwarp();

        float o0 = ob0, o1 = ob1;
#pragma unroll 8
        for (int s = 0; s < 64; s++) {
            float pv = shp[warp][s];
            o0 = fmaf(wq[s][lane], pv, o0);
            o1 = fmaf(wq[s][lane + 32], pv, o1);
        }
        int px = (it << 3) + warp;
        sho[lane][px] = o0;
        sho[lane + 32][px] = o1;
        __syncwarp();
    }
    __syncthreads();

    // fully-coalesced RMW: 64 consecutive pixels per channel
    int bb = pbase >> 12;
    int hw0 = pbase & 4095;
    for (int i = tid; i < 4096; i += 256) {
        int c = i >> 6, px = i & 63;
        int idx = ((bb * 64 + c) << 12) + hw0 + px;
        out[idx] += sho[c][px];
    }
}

// ---------------- launch ----------------
extern "C" void kernel_launch(void* const* d_in, const int* in_sizes, int n_in,
                              void* d_out, int out_size) {
    const float* x     = (const float*)d_in[0];
    const float* style = (const float*)d_in[1];
    const float* wd    = (const float*)d_in[2];   // data_proj_w [6,576]
    const float* db    = (const float*)d_in[3];   // data_proj_b [6]
    const float* sw    = (const float*)d_in[4];   // style_to_data_w [6,128]
    const float* sb    = (const float*)d_in[5];   // style_to_data_b [6]
    const float* qcnn  = (const float*)d_in[6];   // [2,6,2,3]
    const float* meas  = (const float*)d_in[7];   // [6,3]
    const float* ow    = (const float*)d_in[8];   // out_proj_w [64,6]
    const float* ob    = (const float*)d_in[9];   // out_proj_b [64]
    const float* wr    = (const float*)d_in[10];  // res_proj_w [64,576]
    const float* rb    = (const float*)d_in[11];  // res_proj_b [64]
    float* out = (float*)d_out;

    k_setup<<<1, 256>>>(style, sw, sb, qcnn, meas, ow);
    k_conv<<<128, 512>>>(x, wr, rb, wd, db, out);
    k_quant<<<512, 256>>>(ob, out);
}

// round 4
// speedup vs baseline: 1.6375x; 1.6375x over previous
#include <cuda_runtime.h>
#include <cstdint>

#define PI_F 3.14159265358979f

// ---------------- device-global scratch (allocation-free) ----------------
__device__ float d_phi[32768 * 6];          // per-pixel per-wire encoding angle
__device__ float d_Bfrag[72 * 9 * 32 * 2];  // B fragments [kt][nt][lane][2], tf32-rounded
__device__ float d_phiadd[48];              // [b][wire] = pi*tanh(style) + alpha0

__device__ __forceinline__ uint32_t f2tf32(float f) {
    uint32_t r;
    asm("cvt.rna.tf32.f32 %0, %1;" : "=r"(r) : "f"(f));
    return r;
}

__device__ __forceinline__ void mma8(float* d, const uint32_t* a, const uint32_t* b) {
    asm volatile(
        "mma.sync.aligned.m16n8k8.row.col.f32.tf32.tf32.f32 "
        "{%0,%1,%2,%3}, {%4,%5,%6,%7}, {%8,%9}, {%0,%1,%2,%3};"
        : "+f"(d[0]), "+f"(d[1]), "+f"(d[2]), "+f"(d[3])
        : "r"(a[0]), "r"(a[1]), "r"(a[2]), "r"(a[3]), "r"(b[0]), "r"(b[1]));
}

// ---------------- prep: B fragments + style angles ----------------
// grid 73, block 288. Blocks 0..71: kt slice of B_frag. Block 72: style dots.
__global__ void k_prep(const float* __restrict__ wr, const float* __restrict__ wd,
                       const float* __restrict__ style, const float* __restrict__ sw,
                       const float* __restrict__ sb, const float* __restrict__ qcnn) {
    int blk = blockIdx.x;
    int t = threadIdx.x;
    if (blk < 72) {
        int nt = t >> 5, lane = t & 31;
        int n = nt * 8 + (lane >> 2);
        int kin = lane & 3;
        float v[2];
#pragma unroll
        for (int r = 0; r < 2; r++) {
            int kcol = blk * 8 + kin + 4 * r;
            float val = 0.f;
            if (n < 64) val = wr[n * 576 + kcol];
            else if (n < 70) val = wd[(n - 64) * 576 + kcol];
            v[r] = __uint_as_float(f2tf32(val));
        }
        int off = ((blk * 9 + nt) * 32 + lane) * 2;
        d_Bfrag[off] = v[0];
        d_Bfrag[off + 1] = v[1];
    } else {
        int warp = t >> 5, lane = t & 31;
        const unsigned F = 0xffffffffu;
        for (int task = warp; task < 48; task += 9) {
            int bi = task / 6, i = task - bi * 6;
            float4 a = reinterpret_cast<const float4*>(style + bi * 128)[lane];
            float4 w = reinterpret_cast<const float4*>(sw + i * 128)[lane];
            float acc = a.x * w.x + a.y * w.y + a.z * w.z + a.w * w.w;
#pragma unroll
            for (int o = 16; o; o >>= 1) acc += __shfl_xor_sync(F, acc, o);
            if (lane == 0)
                d_phiadd[task] = PI_F * tanhf(acc + sb[i]) + qcnn[i * 6];
        }
    }
}

// ---------------- conv via mma.sync tf32 ----------------
// grid 147 CTAs x 448 thr (14 warps). CTA = 224 px x 72 outputs, K=576 (8 chunks of 72).
// warp wid: pxg = wid>>1 (2 m-tiles of 16 px), cog = wid&1 (nt 0..3 or 4..8).
#define A_BYTES (9 * 14 * 32 * 16)     // 64512
#define B_BYTES (9 * 9 * 32 * 8)       // 20736
#define CONV_SMEM (A_BYTES + B_BYTES)  // 85248

__global__ __launch_bounds__(448, 1) void k_conv(
    const float* __restrict__ x, const float* __restrict__ rb,
    const float* __restrict__ db, float* __restrict__ out) {
    extern __shared__ char smem[];
    char* smA = smem;
    char* smB = smem + A_BYTES;

    int tid = threadIdx.x;
    int lane = tid & 31;
    int wid = tid >> 5;           // 0..13; doubles as mt for the A-build
    int g = lane >> 2, t4 = lane & 3;
    int px0 = blockIdx.x * 224;

    float acc[2][5][4];
#pragma unroll
    for (int m = 0; m < 2; m++)
#pragma unroll
        for (int j = 0; j < 5; j++)
#pragma unroll
            for (int c = 0; c < 4; c++) acc[m][j][c] = 0.f;

    int pxg = wid >> 1, cog = wid & 1;
    int ntbase = cog ? 4 : 0, ntcnt = cog ? 5 : 4;

    for (int chunk = 0; chunk < 8; chunk++) {
        __syncthreads();
        // copy B chunk (coalesced float4)
        {
            const float4* bsrc = reinterpret_cast<const float4*>(d_Bfrag + chunk * 5184);
            float4* bdst = reinterpret_cast<float4*>(smB);
            for (int i = tid; i < 1296; i += 448) bdst[i] = bsrc[i];
        }
        // build A fragments: thread owns (mt=wid, lane), loops kt=0..8
#pragma unroll 3
        for (int kt = 0; kt < 9; kt++) {
            uint32_t vv[4];
#pragma unroll
            for (int half = 0; half < 2; half++) {
                int kloc = kt * 8 + t4 + 4 * half;
                int ci = chunk * 8 + kloc / 9;
                int kk = kloc % 9;
                int kh = kk / 3, kw = kk - kh * 3;
#pragma unroll
                for (int rr = 0; rr < 2; rr++) {
                    int px = wid * 16 + g + 8 * rr;
                    int gpix = px0 + px;
                    int b = gpix >> 12, hw = gpix & 4095;
                    int gh = (hw >> 6) - 1 + kh;
                    int gw = (hw & 63) - 1 + kw;
                    float val = 0.f;
                    if (gpix < 32768 && (unsigned)gh < 64u && (unsigned)gw < 64u)
                        val = __ldg(x + (((b << 6) + ci) << 12) + (gh << 6) + gw);
                    vv[half * 2 + rr] = f2tf32(val);
                }
            }
            // reg order: [0]=(g,t4) [1]=(g+8,t4) [2]=(g,t4+4) [3]=(g+8,t4+4)
            *reinterpret_cast<uint4*>(smA + ((kt * 14 + wid) * 32 + lane) * 16) =
                make_uint4(vv[0], vv[1], vv[2], vv[3]);
        }
        __syncthreads();
        // mma phase
#pragma unroll 3
        for (int kt = 0; kt < 9; kt++) {
            uint4 a0 = *reinterpret_cast<const uint4*>(
                smA + ((kt * 14 + pxg * 2) * 32 + lane) * 16);
            uint4 a1 = *reinterpret_cast<const uint4*>(
                smA + ((kt * 14 + pxg * 2 + 1) * 32 + lane) * 16);
            uint32_t A0[4] = {a0.x, a0.y, a0.z, a0.w};
            uint32_t A1[4] = {a1.x, a1.y, a1.z, a1.w};
#pragma unroll
            for (int j = 0; j < 5; j++) {
                if (j >= ntcnt) break;
                int nt = ntbase + j;
                uint2 bb = *reinterpret_cast<const uint2*>(
                    smB + ((kt * 9 + nt) * 32 + lane) * 8);
                uint32_t B[2] = {bb.x, bb.y};
                mma8(acc[0][j], A0, B);
                mma8(acc[1][j], A1, B);
            }
        }
    }

    // epilogue
#pragma unroll
    for (int m = 0; m < 2; m++) {
        int mt = pxg * 2 + m;
#pragma unroll
        for (int j = 0; j < 5; j++) {
            if (j >= ntcnt) break;
            int nt = ntbase + j;
#pragma unroll
            for (int c = 0; c < 4; c++) {
                int px = mt * 16 + g + 8 * (c >> 1);
                int co = nt * 8 + 2 * t4 + (c & 1);
                int gpix = px0 + px;
                if (gpix >= 32768) continue;
                float dv = acc[m][j][c];
                if (co < 64) {
                    out[(((gpix >> 12) << 6) + co) * 4096 + (gpix & 4095)] =
                        dv + __ldg(rb + co);
                } else if (co < 70) {
                    int wire = co - 64;
                    d_phi[gpix * 6 + wire] =
                        PI_F * tanhf(dv + __ldg(db + wire)) +
                        d_phiadd[(gpix >> 12) * 6 + wire];
                }
            }
        }
    }
}

// ---------------- quantum sim: warp per pixel, 2 amps per lane ----------------
__device__ __forceinline__ void gate_b5(const float2* G,
                                        float& a0r, float& a0i, float& a1r, float& a1i) {
    float2 g00 = G[0], g01 = G[1], g10 = G[2], g11 = G[3];
    float n0r = g00.x * a0r - g00.y * a0i + g01.x * a1r - g01.y * a1i;
    float n0i = g00.x * a0i + g00.y * a0r + g01.x * a1i + g01.y * a1r;
    float n1r = g10.x * a0r - g10.y * a0i + g11.x * a1r - g11.y * a1i;
    float n1i = g10.x * a0i + g10.y * a0r + g11.x * a1i + g11.y * a1r;
    a0r = n0r; a0i = n0i; a1r = n1r; a1i = n1i;
}

__device__ __forceinline__ void gate_lo(int bbit, int lane, const float2* G,
                                        float& a0r, float& a0i, float& a1r, float& a1i) {
    const unsigned F = 0xffffffffu;
    float2 g00 = G[0], g01 = G[1], g10 = G[2], g11 = G[3];
    int m = 1 << bbit;
    float p0r = __shfl_xor_sync(F, a0r, m);
    float p0i = __shfl_xor_sync(F, a0i, m);
    float p1r = __shfl_xor_sync(F, a1r, m);
    float p1i = __shfl_xor_sync(F, a1i, m);
    bool hi = (lane >> bbit) & 1;
    float Ar = hi ? g11.x : g00.x, Ai = hi ? g11.y : g00.y;
    float Pr = hi ? g10.x : g01.x, Pi = hi ? g10.y : g01.y;
    float n0r = Ar * a0r - Ai * a0i + Pr * p0r - Pi * p0i;
    float n0i = Ar * a0i + Ai * a0r + Pr * p0i + Pi * p0r;
    float n1r = Ar * a1r - Ai * a1i + Pr * p1r - Pi * p1i;
    float n1i = Ar * a1i + Ai * a1r + Pr * p1i + Pi * p1r;
    a0r = n0r; a0i = n0i; a1r = n1r; a1i = n1i;
}

__device__ __forceinline__ int ring_src(int s) {
    int b5 = (s >> 5) & 1, b4 = (s >> 4) & 1, b3 = (s >> 3) & 1;
    int b2 = (s >> 2) & 1, b1 = (s >> 1) & 1, b0 = s & 1;
    b5 ^= b0; b0 ^= b1; b1 ^= b2; b2 ^= b3; b3 ^= b4; b4 ^= b5;
    return (b5 << 5) | (b4 << 4) | (b3 << 3) | (b2 << 2) | (b1 << 1) | b0;
}

__device__ __forceinline__ void ring2(int q0l, int q0h, int q1l, int q1h,
                                      float& a0r, float& a0i, float& a1r, float& a1i) {
    const unsigned F = 0xffffffffu;
    float x0r = __shfl_sync(F, a0r, q0l);
    float y0r = __shfl_sync(F, a1r, q0l);
    float x0i = __shfl_sync(F, a0i, q0l);
    float y0i = __shfl_sync(F, a1i, q0l);
    float x1r = __shfl_sync(F, a0r, q1l);
    float y1r = __shfl_sync(F, a1r, q1l);
    float x1i = __shfl_sync(F, a0i, q1l);
    float y1i = __shfl_sync(F, a1i, q1l);
    a0r = q0h ? y0r : x0r; a0i = q0h ? y0i : x0i;
    a1r = q1h ? y1r : x1r; a1i = q1h ? y1i : x1i;
}

// grid 512; block 256 (8 warps); block handles 64 consecutive pixels.
__global__ __launch_bounds__(256) void k_quant(
    const float* __restrict__ ob, const float* __restrict__ qcnn,
    const float* __restrict__ meas, const float* __restrict__ ow,
    float* __restrict__ out) {
    __shared__ float wq[64][64];
    __shared__ float shp[8][64];
    __shared__ float sho[64][65];
    __shared__ float2 s_g1[6][4], s_g2[6][4];
    __shared__ float s_cb0[6], s_sb0[6];
    const unsigned F = 0xffffffffu;
    int tid = threadIdx.x;

    if (tid < 6) {
        int i = tid;
        float b0 = qcnn[(i * 2 + 1) * 3];
        s_cb0[i] = cosf(0.5f * b0);
        s_sb0[i] = sinf(0.5f * b0);
        float a1 = qcnn[((6 + i) * 2 + 0) * 3];
        float b1 = qcnn[((6 + i) * 2 + 1) * 3];
        float ca = cosf(0.5f * a1), sa = sinf(0.5f * a1);
        float cb = cosf(0.5f * b1), sbv = sinf(0.5f * b1);
        s_g1[i][0] = make_float2(cb * ca, -sbv * ca);
        s_g1[i][1] = make_float2(-cb * sa, sbv * sa);
        s_g1[i][2] = make_float2(cb * sa, sbv * sa);
        s_g1[i][3] = make_float2(cb * ca, sbv * ca);
        float th = meas[i * 3 + 0], phv = meas[i * 3 + 1], la = meas[i * 3 + 2];
        float ct = cosf(0.5f * th), st = sinf(0.5f * th);
        s_g2[i][0] = make_float2(ct, 0.f);
        s_g2[i][1] = make_float2(-cosf(la) * st, -sinf(la) * st);
        s_g2[i][2] = make_float2(cosf(phv) * st, sinf(phv) * st);
        s_g2[i][3] = make_float2(cosf(phv + la) * ct, sinf(phv + la) * ct);
    }
    for (int idx = tid; idx < 4096; idx += 256) {
        int s = idx >> 6, c = idx & 63;
        float acc = 0.f;
#pragma unroll
        for (int i = 0; i < 6; i++)
            acc += ow[c * 6 + i] * (((s >> (5 - i)) & 1) ? -1.f : 1.f);
        wq[s][c] = acc;
    }

    int warp = tid >> 5, lane = tid & 31;
    int q0 = ring_src(lane), q1 = ring_src(lane + 32);
    int q0l = q0 & 31, q0h = q0 >> 5;
    int q1l = q1 & 31, q1h = q1 >> 5;
    float ob0 = ob[lane], ob1 = ob[lane + 32];
    int pbase = blockIdx.x << 6;
    __syncthreads();

    for (int it = 0; it < 8; it++) {
        int p = pbase + (it << 3) + warp;
        float myphi = 0.f;
        if (lane < 6) myphi = d_phi[p * 6 + lane];

        float u0r[6], u0i[6], u1r[6], u1i[6];
#pragma unroll
        for (int i = 0; i < 6; i++) {
            float ph = __shfl_sync(F, myphi, i);
            float sv, cv;
            __sincosf(0.5f * ph, &sv, &cv);
            float cb = s_cb0[i], sb = s_sb0[i];
            u0r[i] = cv * cb; u0i[i] = -cv * sb;
            u1r[i] = sv * cb; u1i[i] = sv * sb;
        }
        float a0r = 1.f, a0i = 0.f, a1r, a1i;
#pragma unroll
        for (int i = 0; i < 6; i++) {
            int bit = (lane >> (5 - i)) & 1;
            float ur = bit ? u1r[i] : u0r[i];
            float ui = bit ? u1i[i] : u0i[i];
            float nr = a0r * ur - a0i * ui;
            float ni = a0r * ui + a0i * ur;
            a0r = nr; a0i = ni;
        }
        a1r = u1r[0]; a1i = u1i[0];
#pragma unroll
        for (int i = 1; i < 6; i++) {
            int bit = (lane >> (5 - i)) & 1;
            float ur = bit ? u1r[i] : u0r[i];
            float ui = bit ? u1i[i] : u0i[i];
            float nr = a1r * ur - a1i * ui;
            float ni = a1r * ui + a1i * ur;
            a1r = nr; a1i = ni;
        }

        ring2(q0l, q0h, q1l, q1h, a0r, a0i, a1r, a1i);
#pragma unroll
        for (int i = 0; i < 6; i++) {
            if (i == 0) gate_b5(s_g1[0], a0r, a0i, a1r, a1i);
            else        gate_lo(5 - i, lane, s_g1[i], a0r, a0i, a1r, a1i);
        }
        ring2(q0l, q0h, q1l, q1h, a0r, a0i, a1r, a1i);
#pragma unroll
        for (int i = 0; i < 6; i++) {
            if (i == 0) gate_b5(s_g2[0], a0r, a0i, a1r, a1i);
            else        gate_lo(5 - i, lane, s_g2[i], a0r, a0i, a1r, a1i);
        }

        shp[warp][lane] = a0r * a0r + a0i * a0i;
        shp[warp][lane + 32] = a1r * a1r + a1i * a1i;
        __syncwarp();

        float o0 = ob0, o1 = ob1;
#pragma unroll 8
        for (int s = 0; s < 64; s++) {
            float pv = shp[warp][s];
            o0 = fmaf(wq[s][lane], pv, o0);
            o1 = fmaf(wq[s][lane + 32], pv, o1);
        }
        int px = (it << 3) + warp;
        sho[lane][px] = o0;
        sho[lane + 32][px] = o1;
        __syncwarp();
    }
    __syncthreads();

    int bb = pbase >> 12;
    int hw0 = pbase & 4095;
    for (int i = tid; i < 4096; i += 256) {
        int c = i >> 6, px = i & 63;
        int idx = (((bb << 6) + c) << 12) + hw0 + px;
        out[idx] += sho[c][px];
    }
}

// ---------------- launch ----------------
extern "C" void kernel_launch(void* const* d_in, const int* in_sizes, int n_in,
                              void* d_out, int out_size) {
    const float* x     = (const float*)d_in[0];
    const float* style = (const float*)d_in[1];
    const float* wd    = (const float*)d_in[2];   // data_proj_w [6,576]
    const float* db    = (const float*)d_in[3];   // data_proj_b [6]
    const float* sw    = (const float*)d_in[4];   // style_to_data_w [6,128]
    const float* sb    = (const float*)d_in[5];   // style_to_data_b [6]
    const float* qcnn  = (const float*)d_in[6];   // [2,6,2,3]
    const float* meas  = (const float*)d_in[7];   // [6,3]
    const float* ow    = (const float*)d_in[8];   // out_proj_w [64,6]
    const float* ob    = (const float*)d_in[9];   // out_proj_b [64]
    const float* wr    = (const float*)d_in[10];  // res_proj_w [64,576]
    const float* rb    = (const float*)d_in[11];  // res_proj_b [64]
    float* out = (float*)d_out;

    cudaFuncSetAttribute(k_conv, cudaFuncAttributeMaxDynamicSharedMemorySize, CONV_SMEM);
    k_prep<<<73, 288>>>(wr, wd, style, sw, sb, qcnn);
    k_conv<<<147, 448, CONV_SMEM>>>(x, rb, db, out);
    k_quant<<<512, 256>>>(ob, qcnn, meas, ow, out);
}

// round 5
// speedup vs baseline: 2.0675x; 1.2626x over previous
#include <cuda_runtime.h>
#include <cstdint>

#define PI_F 3.14159265358979f

__device__ __forceinline__ uint32_t f2tf32(float f) {
    uint32_t r;
    asm("cvt.rna.tf32.f32 %0, %1;" : "=r"(r) : "f"(f));
    return r;
}

__device__ __forceinline__ void mma8(float* d, const uint32_t* a, const uint32_t* b) {
    asm volatile(
        "mma.sync.aligned.m16n8k8.row.col.f32.tf32.tf32.f32 "
        "{%0,%1,%2,%3}, {%4,%5,%6,%7}, {%8,%9}, {%0,%1,%2,%3};"
        : "+f"(d[0]), "+f"(d[1]), "+f"(d[2]), "+f"(d[3])
        : "r"(a[0]), "r"(a[1]), "r"(a[2]), "r"(a[3]), "r"(b[0]), "r"(b[1]));
}

// ---------------- quantum gate helpers (warp-collective, 2 amps/lane) ----------------
__device__ __forceinline__ void gate_b5(const float2* G,
                                        float& a0r, float& a0i, float& a1r, float& a1i) {
    float2 g00 = G[0], g01 = G[1], g10 = G[2], g11 = G[3];
    float n0r = g00.x * a0r - g00.y * a0i + g01.x * a1r - g01.y * a1i;
    float n0i = g00.x * a0i + g00.y * a0r + g01.x * a1i + g01.y * a1r;
    float n1r = g10.x * a0r - g10.y * a0i + g11.x * a1r - g11.y * a1i;
    float n1i = g10.x * a0i + g10.y * a0r + g11.x * a1i + g11.y * a1r;
    a0r = n0r; a0i = n0i; a1r = n1r; a1i = n1i;
}

__device__ __forceinline__ void gate_lo(int bbit, int lane, const float2* G,
                                        float& a0r, float& a0i, float& a1r, float& a1i) {
    const unsigned F = 0xffffffffu;
    float2 g00 = G[0], g01 = G[1], g10 = G[2], g11 = G[3];
    int m = 1 << bbit;
    float p0r = __shfl_xor_sync(F, a0r, m);
    float p0i = __shfl_xor_sync(F, a0i, m);
    float p1r = __shfl_xor_sync(F, a1r, m);
    float p1i = __shfl_xor_sync(F, a1i, m);
    bool hi = (lane >> bbit) & 1;
    float Ar = hi ? g11.x : g00.x, Ai = hi ? g11.y : g00.y;
    float Pr = hi ? g10.x : g01.x, Pi = hi ? g10.y : g01.y;
    float n0r = Ar * a0r - Ai * a0i + Pr * p0r - Pi * p0i;
    float n0i = Ar * a0i + Ai * a0r + Pr * p0i + Pi * p0r;
    float n1r = Ar * a1r - Ai * a1i + Pr * p1r - Pi * p1i;
    float n1i = Ar * a1i + Ai * a1r + Pr * p1i + Pi * p1r;
    a0r = n0r; a0i = n0i; a1r = n1r; a1i = n1i;
}

__device__ __forceinline__ int ring_src(int s) {
    int b5 = (s >> 5) & 1, b4 = (s >> 4) & 1, b3 = (s >> 3) & 1;
    int b2 = (s >> 2) & 1, b1 = (s >> 1) & 1, b0 = s & 1;
    b5 ^= b0; b0 ^= b1; b1 ^= b2; b2 ^= b3; b3 ^= b4; b4 ^= b5;
    return (b5 << 5) | (b4 << 4) | (b3 << 3) | (b2 << 2) | (b1 << 1) | b0;
}

__device__ __forceinline__ void ring2(int q0l, int q0h, int q1l, int q1h,
                                      float& a0r, float& a0i, float& a1r, float& a1i) {
    const unsigned F = 0xffffffffu;
    float x0r = __shfl_sync(F, a0r, q0l);
    float y0r = __shfl_sync(F, a1r, q0l);
    float x0i = __shfl_sync(F, a0i, q0l);
    float y0i = __shfl_sync(F, a1i, q0l);
    float x1r = __shfl_sync(F, a0r, q1l);
    float y1r = __shfl_sync(F, a1r, q1l);
    float x1i = __shfl_sync(F, a0i, q1l);
    float y1i = __shfl_sync(F, a1i, q1l);
    a0r = q0h ? y0r : x0r; a0i = q0h ? y0i : x0i;
    a1r = q1h ? y1r : x1r; a1i = q1h ? y1i : x1i;
}

// ---------------- fused kernel ----------------
// 256 CTAs x 256 thr (8 warps). CTA = 128 px x 72 outputs (64 res + 6 angle + 2 pad).
// K=576 in 8 chunks of 72 (9 k-tiles of 8). Warp wid owns m-tile wid (16 px), all 9 nt.
#define A_BYTES (9 * 8 * 32 * 16)     // 36864
#define B_BYTES (9 * 9 * 32 * 8)      // 20736
#define FUSED_SMEM (A_BYTES + B_BYTES)

__global__ __launch_bounds__(256, 2) void k_fused(
    const float* __restrict__ x, const float* __restrict__ wr,
    const float* __restrict__ wd, const float* __restrict__ rb,
    const float* __restrict__ db, const float* __restrict__ style,
    const float* __restrict__ sw, const float* __restrict__ sb,
    const float* __restrict__ qcnn, const float* __restrict__ meas,
    const float* __restrict__ ow, const float* __restrict__ ob,
    float* __restrict__ out) {
    extern __shared__ char smem[];
    char* smA = smem;                 // A frags [kt][mt][lane] uint4
    char* smB = smem + A_BYTES;       // B frags [kt][nt][lane] uint2; reused for phi in tail
    __shared__ float s_phiadd[6];
    __shared__ float s_cb0[6], s_sb0[6];
    __shared__ float2 s_g1[6][4], s_g2[6][4];

    const unsigned F = 0xffffffffu;
    int tid = threadIdx.x;
    int lane = tid & 31;
    int wid = tid >> 5;               // warp = m-tile
    int g = lane >> 2, t4 = lane & 3;
    int px0 = blockIdx.x << 7;
    int b = px0 >> 12;
    int hwbase = px0 & 4095;

    // --- small tables ---
    if (tid < 6) {
        int i = tid;
        float b0 = qcnn[i * 6 + 3];
        s_cb0[i] = cosf(0.5f * b0);
        s_sb0[i] = sinf(0.5f * b0);
        float a1 = qcnn[36 + i * 6];
        float b1 = qcnn[36 + i * 6 + 3];
        float ca = cosf(0.5f * a1), sa = sinf(0.5f * a1);
        float cb = cosf(0.5f * b1), sbv = sinf(0.5f * b1);
        s_g1[i][0] = make_float2(cb * ca, -sbv * ca);
        s_g1[i][1] = make_float2(-cb * sa, sbv * sa);
        s_g1[i][2] = make_float2(cb * sa, sbv * sa);
        s_g1[i][3] = make_float2(cb * ca, sbv * ca);
        float th = meas[i * 3 + 0], phv = meas[i * 3 + 1], la = meas[i * 3 + 2];
        float ct = cosf(0.5f * th), st = sinf(0.5f * th);
        s_g2[i][0] = make_float2(ct, 0.f);
        s_g2[i][1] = make_float2(-cosf(la) * st, -sinf(la) * st);
        s_g2[i][2] = make_float2(cosf(phv) * st, sinf(phv) * st);
        s_g2[i][3] = make_float2(cosf(phv + la) * ct, sinf(phv + la) * ct);
    }
    if (wid < 6) {   // style projection for this batch image, wire = wid
        float4 a = reinterpret_cast<const float4*>(style + b * 128)[lane];
        float4 w = reinterpret_cast<const float4*>(sw + wid * 128)[lane];
        float acc = a.x * w.x + a.y * w.y + a.z * w.z + a.w * w.w;
#pragma unroll
        for (int o = 16; o; o >>= 1) acc += __shfl_xor_sync(F, acc, o);
        if (lane == 0)
            s_phiadd[wid] = PI_F * tanhf(acc + sb[wid]) + qcnn[wid * 6];
    }

    float acc[9][4];
#pragma unroll
    for (int j = 0; j < 9; j++)
#pragma unroll
        for (int c = 0; c < 4; c++) acc[j][c] = 0.f;

    // --- mainloop over K chunks ---
    for (int chunk = 0; chunk < 8; chunk++) {
        __syncthreads();
        // B fragments: tf32-convert weights in place (L2-resident)
        for (int i = tid; i < 2592; i += 256) {
            int kt = i / 288;
            int r = i - kt * 288;
            int nt = r >> 5, ln = r & 31;
            int n = nt * 8 + (ln >> 2);
            int kbase = chunk * 72 + kt * 8 + (ln & 3);
            float v0 = 0.f, v1 = 0.f;
            if (n < 64) {
                v0 = __ldg(wr + n * 576 + kbase);
                v1 = __ldg(wr + n * 576 + kbase + 4);
            } else if (n < 70) {
                v0 = __ldg(wd + (n - 64) * 576 + kbase);
                v1 = __ldg(wd + (n - 64) * 576 + kbase + 4);
            }
            *reinterpret_cast<uint2*>(smB + ((kt * 9 + nt) * 32 + ln) * 8) =
                make_uint2(f2tf32(v0), f2tf32(v1));
        }
        // A fragments: direct im2col from global (heavy L1 reuse)
#pragma unroll 3
        for (int kt = 0; kt < 9; kt++) {
            uint32_t vv[4];
#pragma unroll
            for (int half = 0; half < 2; half++) {
                int kloc = kt * 8 + t4 + 4 * half;
                int ci = chunk * 8 + kloc / 9;
                int kk = kloc % 9;
                int kh = kk / 3, kw = kk - kh * 3;
#pragma unroll
                for (int rr = 0; rr < 2; rr++) {
                    int px = wid * 16 + g + 8 * rr;
                    int hw = hwbase + px;
                    int gh = (hw >> 6) - 1 + kh;
                    int gw = (hw & 63) - 1 + kw;
                    float val = 0.f;
                    if ((unsigned)gh < 64u && (unsigned)gw < 64u)
                        val = __ldg(x + (((b << 6) + ci) << 12) + (gh << 6) + gw);
                    vv[half * 2 + rr] = f2tf32(val);
                }
            }
            *reinterpret_cast<uint4*>(smA + ((kt * 8 + wid) * 32 + lane) * 16) =
                make_uint4(vv[0], vv[1], vv[2], vv[3]);
        }
        __syncthreads();
        // mma phase
#pragma unroll 3
        for (int kt = 0; kt < 9; kt++) {
            uint4 a4 = *reinterpret_cast<const uint4*>(
                smA + ((kt * 8 + wid) * 32 + lane) * 16);
            uint32_t A[4] = {a4.x, a4.y, a4.z, a4.w};
#pragma unroll
            for (int nt = 0; nt < 9; nt++) {
                uint2 bb = *reinterpret_cast<const uint2*>(
                    smB + ((kt * 9 + nt) * 32 + lane) * 8);
                uint32_t B[2] = {bb.x, bb.y};
                mma8(acc[nt], A, B);
            }
        }
    }
    __syncthreads();   // all mma done; smA/smB free for tail scratch

    // --- phi staging: nt=8 holds channels 64..71 (angle wires 0..5 at t4<3) ---
    float* sphi = (float*)(smB + wid * 512);     // [16 px][6 wires]
    if (t4 < 3) {
#pragma unroll
        for (int c = 0; c < 4; c++) {
            int pxl = g + 8 * (c >> 1);
            int wire = 2 * t4 + (c & 1);
            sphi[pxl * 6 + wire] =
                PI_F * tanhf(acc[8][c] + __ldg(db + wire)) + s_phiadd[wire];
        }
    }
    __syncwarp();

    // --- circuit per pixel (warp-collective), stage quant outputs ---
    float* stg = (float*)(smA + wid * 4352);     // [16 px][68] floats (pad)
    int q0 = ring_src(lane), q1 = ring_src(lane + 32);
    int q0l = q0 & 31, q0h = q0 >> 5;
    int q1l = q1 & 31, q1h = q1 >> 5;
    float obr0 = __ldg(ob + lane), obr1 = __ldg(ob + lane + 32);
    float owA[6], owB[6];
#pragma unroll
    for (int i = 0; i < 6; i++) {
        owA[i] = __ldg(ow + lane * 6 + i);
        owB[i] = __ldg(ow + (lane + 32) * 6 + i);
    }

    for (int pxl = 0; pxl < 16; pxl++) {
        float myphi = (lane < 6) ? sphi[pxl * 6 + lane] : 0.f;

        float u0r[6], u0i[6], u1r[6], u1i[6];
#pragma unroll
        for (int i = 0; i < 6; i++) {
            float ph = __shfl_sync(F, myphi, i);
            float sv, cv;
            __sincosf(0.5f * ph, &sv, &cv);
            float cb = s_cb0[i], sbv = s_sb0[i];
            u0r[i] = cv * cb; u0i[i] = -cv * sbv;
            u1r[i] = sv * cb; u1i[i] = sv * sbv;
        }
        float a0r = 1.f, a0i = 0.f, a1r, a1i;
#pragma unroll
        for (int i = 0; i < 6; i++) {
            int bit = (lane >> (5 - i)) & 1;
            float ur = bit ? u1r[i] : u0r[i];
            float ui = bit ? u1i[i] : u0i[i];
            float nr = a0r * ur - a0i * ui;
            float ni = a0r * ui + a0i * ur;
            a0r = nr; a0i = ni;
        }
        a1r = u1r[0]; a1i = u1i[0];
#pragma unroll
        for (int i = 1; i < 6; i++) {
            int bit = (lane >> (5 - i)) & 1;
            float ur = bit ? u1r[i] : u0r[i];
            float ui = bit ? u1i[i] : u0i[i];
            float nr = a1r * ur - a1i * ui;
            float ni = a1r * ui + a1i * ur;
            a1r = nr; a1i = ni;
        }

        ring2(q0l, q0h, q1l, q1h, a0r, a0i, a1r, a1i);
#pragma unroll
        for (int i = 0; i < 6; i++) {
            if (i == 0) gate_b5(s_g1[0], a0r, a0i, a1r, a1i);
            else        gate_lo(5 - i, lane, s_g1[i], a0r, a0i, a1r, a1i);
        }
        ring2(q0l, q0h, q1l, q1h, a0r, a0i, a1r, a1i);
#pragma unroll
        for (int i = 0; i < 6; i++) {
            if (i == 0) gate_b5(s_g2[0], a0r, a0i, a1r, a1i);
            else        gate_lo(5 - i, lane, s_g2[i], a0r, a0i, a1r, a1i);
        }

        float p0 = a0r * a0r + a0i * a0i;
        float p1 = a1r * a1r + a1i * a1i;
        // PauliZ expvals: wire 0 -> slot bit; wires 1..5 -> lane bits 4..0
        float t0 = p0 + p1;
        float ev[6];
        ev[0] = p0 - p1;
#pragma unroll
        for (int i = 1; i < 6; i++)
            ev[i] = ((lane >> (5 - i)) & 1) ? -t0 : t0;
#pragma unroll
        for (int o = 16; o; o >>= 1)
#pragma unroll
            for (int i = 0; i < 6; i++)
                ev[i] += __shfl_xor_sync(F, ev[i], o);

        float o0 = obr0, o1 = obr1;
#pragma unroll
        for (int i = 0; i < 6; i++) {
            o0 = fmaf(owA[i], ev[i], o0);
            o1 = fmaf(owB[i], ev[i], o1);
        }
        stg[pxl * 68 + lane] = o0;
        stg[pxl * 68 + lane + 32] = o1;
    }
    __syncwarp();

    // --- final write: out = conv + bias + quant, one store per element ---
#pragma unroll
    for (int nt = 0; nt < 8; nt++) {
#pragma unroll
        for (int c = 0; c < 4; c++) {
            int pxl = g + 8 * (c >> 1);
            int co = nt * 8 + 2 * t4 + (c & 1);
            float v = acc[nt][c] + __ldg(rb + co) + stg[pxl * 68 + co];
            out[(((b << 6) + co) << 12) + hwbase + wid * 16 + pxl] = v;
        }
    }
}

// ---------------- launch ----------------
extern "C" void kernel_launch(void* const* d_in, const int* in_sizes, int n_in,
                              void* d_out, int out_size) {
    const float* x     = (const float*)d_in[0];
    const float* style = (const float*)d_in[1];
    const float* wd    = (const float*)d_in[2];   // data_proj_w [6,576]
    const float* db    = (const float*)d_in[3];   // data_proj_b [6]
    const float* sw    = (const float*)d_in[4];   // style_to_data_w [6,128]
    const float* sb    = (const float*)d_in[5];   // style_to_data_b [6]
    const float* qcnn  = (const float*)d_in[6];   // [2,6,2,3]
    const float* meas  = (const float*)d_in[7];   // [6,3]
    const float* ow    = (const float*)d_in[8];   // out_proj_w [64,6]
    const float* ob    = (const float*)d_in[9];   // out_proj_b [64]
    const float* wr    = (const float*)d_in[10];  // res_proj_w [64,576]
    const float* rb    = (const float*)d_in[11];  // res_proj_b [64]
    float* out = (float*)d_out;

    cudaFuncSetAttribute(k_fused, cudaFuncAttributeMaxDynamicSharedMemorySize, FUSED_SMEM);
    k_fused<<<256, 256, FUSED_SMEM>>>(x, wr, wd, rb, db, style, sw, sb,
                                      qcnn, meas, ow, ob, out);
}

// round 6
// speedup vs baseline: 2.1264x; 1.0285x over previous
#include <cuda_runtime.h>
#include <cstdint>

#define PI_F 3.14159265358979f

__device__ __forceinline__ uint32_t f2tf32(float f) {
    uint32_t r;
    asm("cvt.rna.tf32.f32 %0, %1;" : "=r"(r) : "f"(f));
    return r;
}

__device__ __forceinline__ void mma8(float* d, const uint32_t* a, const uint32_t* b) {
    asm volatile(
        "mma.sync.aligned.m16n8k8.row.col.f32.tf32.tf32.f32 "
        "{%0,%1,%2,%3}, {%4,%5,%6,%7}, {%8,%9}, {%0,%1,%2,%3};"
        : "+f"(d[0]), "+f"(d[1]), "+f"(d[2]), "+f"(d[3])
        : "r"(a[0]), "r"(a[1]), "r"(a[2]), "r"(a[3]), "r"(b[0]), "r"(b[1]));
}

// ---------------- quantum gate helpers (warp-collective, 2 amps/lane) ----------------
__device__ __forceinline__ void gate_b5(const float2* G,
                                        float& a0r, float& a0i, float& a1r, float& a1i) {
    float2 g00 = G[0], g01 = G[1], g10 = G[2], g11 = G[3];
    float n0r = g00.x * a0r - g00.y * a0i + g01.x * a1r - g01.y * a1i;
    float n0i = g00.x * a0i + g00.y * a0r + g01.x * a1i + g01.y * a1r;
    float n1r = g10.x * a0r - g10.y * a0i + g11.x * a1r - g11.y * a1i;
    float n1i = g10.x * a0i + g10.y * a0r + g11.x * a1i + g11.y * a1r;
    a0r = n0r; a0i = n0i; a1r = n1r; a1i = n1i;
}

__device__ __forceinline__ void gate_lo(int bbit, int lane, const float2* G,
                                        float& a0r, float& a0i, float& a1r, float& a1i) {
    const unsigned F = 0xffffffffu;
    float2 g00 = G[0], g01 = G[1], g10 = G[2], g11 = G[3];
    int m = 1 << bbit;
    float p0r = __shfl_xor_sync(F, a0r, m);
    float p0i = __shfl_xor_sync(F, a0i, m);
    float p1r = __shfl_xor_sync(F, a1r, m);
    float p1i = __shfl_xor_sync(F, a1i, m);
    bool hi = (lane >> bbit) & 1;
    float Ar = hi ? g11.x : g00.x, Ai = hi ? g11.y : g00.y;
    float Pr = hi ? g10.x : g01.x, Pi = hi ? g10.y : g01.y;
    float n0r = Ar * a0r - Ai * a0i + Pr * p0r - Pi * p0i;
    float n0i = Ar * a0i + Ai * a0r + Pr * p0i + Pi * p0r;
    float n1r = Ar * a1r - Ai * a1i + Pr * p1r - Pi * p1i;
    float n1i = Ar * a1i + Ai * a1r + Pr * p1i + Pi * p1r;
    a0r = n0r; a0i = n0i; a1r = n1r; a1i = n1i;
}

__device__ __forceinline__ int ring_src(int s) {
    int b5 = (s >> 5) & 1, b4 = (s >> 4) & 1, b3 = (s >> 3) & 1;
    int b2 = (s >> 2) & 1, b1 = (s >> 1) & 1, b0 = s & 1;
    b5 ^= b0; b0 ^= b1; b1 ^= b2; b2 ^= b3; b3 ^= b4; b4 ^= b5;
    return (b5 << 5) | (b4 << 4) | (b3 << 3) | (b2 << 2) | (b1 << 1) | b0;
}

__device__ __forceinline__ void ring2(int q0l, int q0h, int q1l, int q1h,
                                      float& a0r, float& a0i, float& a1r, float& a1i) {
    const unsigned F = 0xffffffffu;
    float x0r = __shfl_sync(F, a0r, q0l);
    float y0r = __shfl_sync(F, a1r, q0l);
    float x0i = __shfl_sync(F, a0i, q0l);
    float y0i = __shfl_sync(F, a1i, q0l);
    float x1r = __shfl_sync(F, a0r, q1l);
    float y1r = __shfl_sync(F, a1r, q1l);
    float x1i = __shfl_sync(F, a0i, q1l);
    float y1i = __shfl_sync(F, a1i, q1l);
    a0r = q0h ? y0r : x0r; a0i = q0h ? y0i : x0i;
    a1r = q1h ? y1r : x1r; a1i = q1h ? y1i : x1i;
}

// ---------------- fused kernel ----------------
// 256 CTAs x 256 thr (8 warps). CTA = 128 px (2 image rows) x 72 outputs.
// K=576 in 8 chunks of 72 (9 k-tiles of 8).
// smem (bytes): smA 0..36864 | smB 36864..57600 | xs 57600..66048 | ws 66048..87328
#define SMA_OFF 0
#define SMB_OFF 36864
#define XS_OFF  57600
#define WS_OFF  66048
#define WS_STRIDE 76            // floats; 76 % 32 = 12 -> conflict-free frag build
#define FUSED_SMEM 87328

__global__ __launch_bounds__(256, 2) void k_fused(
    const float* __restrict__ x, const float* __restrict__ wr,
    const float* __restrict__ wd, const float* __restrict__ rb,
    const float* __restrict__ db, const float* __restrict__ style,
    const float* __restrict__ sw, const float* __restrict__ sb,
    const float* __restrict__ qcnn, const float* __restrict__ meas,
    const float* __restrict__ ow, const float* __restrict__ ob,
    float* __restrict__ out) {
    extern __shared__ char smem[];
    char* smA = smem + SMA_OFF;                        // A frags [kt][mt][lane] uint4
    char* smB = smem + SMB_OFF;                        // B frags [kt][nt][lane] uint2
    float (*xs)[4][66] = (float (*)[4][66])(smem + XS_OFF);
    float* ws = (float*)(smem + WS_OFF);               // [70][WS_STRIDE] tf32 weights
    __shared__ float s_phiadd[6];
    __shared__ float s_cb0[6], s_sb0[6];
    __shared__ float2 s_g1[6][4], s_g2[6][4];

    const unsigned F = 0xffffffffu;
    int tid = threadIdx.x;
    int lane = tid & 31;
    int wid = tid >> 5;               // warp = m-tile
    int g = lane >> 2, t4 = lane & 3;
    int px0 = blockIdx.x << 7;
    int b = px0 >> 12;
    int hwbase = px0 & 4095;
    int h0 = hwbase >> 6;             // 128 px = 2 full image rows h0, h0+1

    // --- small tables ---
    if (tid < 6) {
        int i = tid;
        float b0 = qcnn[i * 6 + 3];
        s_cb0[i] = cosf(0.5f * b0);
        s_sb0[i] = sinf(0.5f * b0);
        float a1 = qcnn[36 + i * 6];
        float b1 = qcnn[36 + i * 6 + 3];
        float ca = cosf(0.5f * a1), sa = sinf(0.5f * a1);
        float cb = cosf(0.5f * b1), sbv = sinf(0.5f * b1);
        s_g1[i][0] = make_float2(cb * ca, -sbv * ca);
        s_g1[i][1] = make_float2(-cb * sa, sbv * sa);
        s_g1[i][2] = make_float2(cb * sa, sbv * sa);
        s_g1[i][3] = make_float2(cb * ca, sbv * ca);
        float th = meas[i * 3 + 0], phv = meas[i * 3 + 1], la = meas[i * 3 + 2];
        float ct = cosf(0.5f * th), st = sinf(0.5f * th);
        s_g2[i][0] = make_float2(ct, 0.f);
        s_g2[i][1] = make_float2(-cosf(la) * st, -sinf(la) * st);
        s_g2[i][2] = make_float2(cosf(phv) * st, sinf(phv) * st);
        s_g2[i][3] = make_float2(cosf(phv + la) * ct, sinf(phv + la) * ct);
    }
    if (wid < 6) {   // style projection for this batch image, wire = wid
        float4 a = reinterpret_cast<const float4*>(style + b * 128)[lane];
        float4 w = reinterpret_cast<const float4*>(sw + wid * 128)[lane];
        float acc = a.x * w.x + a.y * w.y + a.z * w.z + a.w * w.w;
#pragma unroll
        for (int o = 16; o; o >>= 1) acc += __shfl_xor_sync(F, acc, o);
        if (lane == 0)
            s_phiadd[wid] = PI_F * tanhf(acc + sb[wid]) + qcnn[wid * 6];
    }

    float acc[9][4];
#pragma unroll
    for (int j = 0; j < 9; j++)
#pragma unroll
        for (int c = 0; c < 4; c++) acc[j][c] = 0.f;

    // --- mainloop over K chunks ---
    for (int chunk = 0; chunk < 8; chunk++) {
        __syncthreads();
        // stage x tile: 8 ci x 4 rows x 66 cols, zero-padded halo (coalesced)
        for (int i = tid; i < 2112; i += 256) {
            int ci = i / 264; int rem = i - ci * 264;
            int r = rem / 66; int cpos = rem - r * 66;
            int gh = h0 - 1 + r, gw = cpos - 1;
            float v = 0.f;
            if ((unsigned)gh < 64u && (unsigned)gw < 64u)
                v = __ldg(x + (((b << 6) + (chunk << 3) + ci) << 12) + (gh << 6) + gw);
            xs[ci][r][cpos] = v;
        }
        // stage weights: 70 rows x 72 cols as float4, tf32-converted
        for (int i = tid; i < 1260; i += 256) {
            int n = i / 18, q = (i - n * 18) << 2;
            const float* src = (n < 64) ? (wr + n * 576) : (wd + (n - 64) * 576);
            float4 v = *reinterpret_cast<const float4*>(src + chunk * 72 + q);
            uint4 t;
            t.x = f2tf32(v.x); t.y = f2tf32(v.y); t.z = f2tf32(v.z); t.w = f2tf32(v.w);
            *reinterpret_cast<uint4*>(ws + n * WS_STRIDE + q) = t;
        }
        __syncthreads();
        // build B fragments from ws (conflict-free LDS)
        for (int i = tid; i < 2592; i += 256) {
            int kt = i / 288;
            int r = i - kt * 288;
            int nt = r >> 5, ln = r & 31;
            int n = nt * 8 + (ln >> 2);
            int k = kt * 8 + (ln & 3);
            uint32_t v0 = 0u, v1 = 0u;
            if (n < 70) {
                v0 = *reinterpret_cast<const uint32_t*>(ws + n * WS_STRIDE + k);
                v1 = *reinterpret_cast<const uint32_t*>(ws + n * WS_STRIDE + k + 4);
            }
            *reinterpret_cast<uint2*>(smB + ((kt * 9 + nt) * 32 + ln) * 8) =
                make_uint2(v0, v1);
        }
        // build A fragments from xs
#pragma unroll 3
        for (int kt = 0; kt < 9; kt++) {
            uint32_t vv[4];
#pragma unroll
            for (int half = 0; half < 2; half++) {
                int kloc = kt * 8 + t4 + 4 * half;
                int ci = kloc / 9;
                int kk = kloc - ci * 9;
                int kh = kk / 3, kw = kk - kh * 3;
#pragma unroll
                for (int rr = 0; rr < 2; rr++) {
                    int px = wid * 16 + g + 8 * rr;
                    int r = (px >> 6) + kh;
                    int cpos = (px & 63) + kw;
                    vv[half * 2 + rr] = f2tf32(xs[ci][r][cpos]);
                }
            }
            *reinterpret_cast<uint4*>(smA + ((kt * 8 + wid) * 32 + lane) * 16) =
                make_uint4(vv[0], vv[1], vv[2], vv[3]);
        }
        __syncthreads();
        // mma phase
#pragma unroll 3
        for (int kt = 0; kt < 9; kt++) {
            uint4 a4 = *reinterpret_cast<const uint4*>(
                smA + ((kt * 8 + wid) * 32 + lane) * 16);
            uint32_t A[4] = {a4.x, a4.y, a4.z, a4.w};
#pragma unroll
            for (int nt = 0; nt < 9; nt++) {
                uint2 bb = *reinterpret_cast<const uint2*>(
                    smB + ((kt * 9 + nt) * 32 + lane) * 8);
                uint32_t B[2] = {bb.x, bb.y};
                mma8(acc[nt], A, B);
            }
        }
    }
    __syncthreads();   // all mma done; smA/smB free for tail scratch

    // --- phi staging: nt=8 holds channels 64..71 (angle wires 0..5 at t4<3) ---
    float* sphi = (float*)(smB + wid * 512);     // [16 px][6 wires]
    if (t4 < 3) {
#pragma unroll
        for (int c = 0; c < 4; c++) {
            int pxl = g + 8 * (c >> 1);
            int wire = 2 * t4 + (c & 1);
            sphi[pxl * 6 + wire] =
                PI_F * tanhf(acc[8][c] + __ldg(db + wire)) + s_phiadd[wire];
        }
    }
    __syncwarp();

    // --- circuit per pixel (warp-collective), stage outputs in stg[px][69] ---
    float* stg = (float*)smA;                    // [128 px][69] floats
    int q0 = ring_src(lane), q1 = ring_src(lane + 32);
    int q0l = q0 & 31, q0h = q0 >> 5;
    int q1l = q1 & 31, q1h = q1 >> 5;
    float obr0 = __ldg(ob + lane), obr1 = __ldg(ob + lane + 32);
    float owA[6], owB[6];
#pragma unroll
    for (int i = 0; i < 6; i++) {
        owA[i] = __ldg(ow + lane * 6 + i);
        owB[i] = __ldg(ow + (lane + 32) * 6 + i);
    }

    for (int pxl = 0; pxl < 16; pxl++) {
        float myphi = (lane < 6) ? sphi[pxl * 6 + lane] : 0.f;

        float u0r[6], u0i[6], u1r[6], u1i[6];
#pragma unroll
        for (int i = 0; i < 6; i++) {
            float ph = __shfl_sync(F, myphi, i);
            float sv, cv;
            __sincosf(0.5f * ph, &sv, &cv);
            float cb = s_cb0[i], sbv = s_sb0[i];
            u0r[i] = cv * cb; u0i[i] = -cv * sbv;
            u1r[i] = sv * cb; u1i[i] = sv * sbv;
        }
        float a0r = 1.f, a0i = 0.f, a1r, a1i;
#pragma unroll
        for (int i = 0; i < 6; i++) {
            int bit = (lane >> (5 - i)) & 1;
            float ur = bit ? u1r[i] : u0r[i];
            float ui = bit ? u1i[i] : u0i[i];
            float nr = a0r * ur - a0i * ui;
            float ni = a0r * ui + a0i * ur;
            a0r = nr; a0i = ni;
        }
        a1r = u1r[0]; a1i = u1i[0];
#pragma unroll
        for (int i = 1; i < 6; i++) {
            int bit = (lane >> (5 - i)) & 1;
            float ur = bit ? u1r[i] : u0r[i];
            float ui = bit ? u1i[i] : u0i[i];
            float nr = a1r * ur - a1i * ui;
            float ni = a1r * ui + a1i * ur;
            a1r = nr; a1i = ni;
        }

        ring2(q0l, q0h, q1l, q1h, a0r, a0i, a1r, a1i);
#pragma unroll
        for (int i = 0; i < 6; i++) {
            if (i == 0) gate_b5(s_g1[0], a0r, a0i, a1r, a1i);
            else        gate_lo(5 - i, lane, s_g1[i], a0r, a0i, a1r, a1i);
        }
        ring2(q0l, q0h, q1l, q1h, a0r, a0i, a1r, a1i);
#pragma unroll
        for (int i = 0; i < 6; i++) {
            if (i == 0) gate_b5(s_g2[0], a0r, a0i, a1r, a1i);
            else        gate_lo(5 - i, lane, s_g2[i], a0r, a0i, a1r, a1i);
        }

        float p0 = a0r * a0r + a0i * a0i;
        float p1 = a1r * a1r + a1i * a1i;
        // Walsh reduction: ev0 = sum(p0-p1); ev_i = F[1<<(5-i)] of (p0+p1)
        float t0 = p0 + p1, dd = p0 - p1;
#pragma unroll
        for (int m = 16; m; m >>= 1) dd += __shfl_xor_sync(F, dd, m);
#pragma unroll
        for (int m = 16; m; m >>= 1) {
            float o = __shfl_xor_sync(F, t0, m);
            t0 = ((lane & m) ? -t0 : t0) + o;
        }
        float e1 = __shfl_sync(F, t0, 16);
        float e2 = __shfl_sync(F, t0, 8);
        float e3 = __shfl_sync(F, t0, 4);
        float e4 = __shfl_sync(F, t0, 2);
        float e5 = __shfl_sync(F, t0, 1);

        float o0 = fmaf(owA[0], dd, obr0);
        float o1 = fmaf(owB[0], dd, obr1);
        o0 = fmaf(owA[1], e1, o0); o1 = fmaf(owB[1], e1, o1);
        o0 = fmaf(owA[2], e2, o0); o1 = fmaf(owB[2], e2, o1);
        o0 = fmaf(owA[3], e3, o0); o1 = fmaf(owB[3], e3, o1);
        o0 = fmaf(owA[4], e4, o0); o1 = fmaf(owB[4], e4, o1);
        o0 = fmaf(owA[5], e5, o0); o1 = fmaf(owB[5], e5, o1);

        int px = wid * 16 + pxl;
        stg[px * 69 + lane] = o0;
        stg[px * 69 + lane + 32] = o1;
    }
    __syncwarp();

    // --- conv epilogue: add conv + bias into stg ---
#pragma unroll
    for (int nt = 0; nt < 8; nt++) {
#pragma unroll
        for (int c = 0; c < 4; c++) {
            int pxl = g + 8 * (c >> 1);
            int co = nt * 8 + 2 * t4 + (c & 1);
            int px = wid * 16 + pxl;
            stg[px * 69 + co] += acc[nt][c] + __ldg(rb + co);
        }
    }
    __syncthreads();

    // --- fully coalesced final write: 64 co rows x 128 contiguous px ---
    for (int i = tid; i < 8192; i += 256) {
        int co = i >> 7, px = i & 127;
        out[(((b << 6) + co) << 12) + hwbase + px] = stg[px * 69 + co];
    }
}

// ---------------- launch ----------------
extern "C" void kernel_launch(void* const* d_in, const int* in_sizes, int n_in,
                              void* d_out, int out_size) {
    const float* x     = (const float*)d_in[0];
    const float* style = (const float*)d_in[1];
    const float* wd    = (const float*)d_in[2];   // data_proj_w [6,576]
    const float* db    = (const float*)d_in[3];   // data_proj_b [6]
    const float* sw    = (const float*)d_in[4];   // style_to_data_w [6,128]
    const float* sb    = (const float*)d_in[5];   // style_to_data_b [6]
    const float* qcnn  = (const float*)d_in[6];   // [2,6,2,3]
    const float* meas  = (const float*)d_in[7];   // [6,3]
    const float* ow    = (const float*)d_in[8];   // out_proj_w [64,6]
    const float* ob    = (const float*)d_in[9];   // out_proj_b [64]
    const float* wr    = (const float*)d_in[10];  // res_proj_w [64,576]
    const float* rb    = (const float*)d_in[11];  // res_proj_b [64]
    float* out = (float*)d_out;

    cudaFuncSetAttribute(k_fused, cudaFuncAttributeMaxDynamicSharedMemorySize, FUSED_SMEM);
    k_fused<<<256, 256, FUSED_SMEM>>>(x, wr, wd, rb, db, style, sw, sb,
                                      qcnn, meas, ow, ob, out);
}